// round 13
// baseline (speedup 1.0000x reference)
#include <cuda_runtime.h>

// AlarmworkRNN collapsed to a vector RNN (only sequence row 2047 matters).
// Round 13: main loop restored to R7's proven-fastest shape (no out-fold),
// out_kernel rebuilt (grid 32, 8 steps/block: 4x less W_out traffic),
// init folded into u_kernel, double-relaxed poll on the barrier.

#define GRID  128
#define BLOCK 512
#define NSTEP 256

__device__ unsigned g_arrive;
__device__ float2 g_z[2][1024];           // parity-buffered {z1, z2}
__device__ float g_U[2][NSTEP][1024];     // u1/u2 per step (bias folded)
__device__ float g_hist[NSTEP][1024];     // z1 history for out_kernel

__device__ __forceinline__ void arrive_release(unsigned* p) {
    asm volatile("red.release.gpu.global.add.u32 [%0], %1;"
                 :: "l"(p), "r"(1u) : "memory");
}
__device__ __forceinline__ unsigned ld_relaxed_gpu(unsigned* p) {
    unsigned v;
    asm volatile("ld.relaxed.gpu.global.u32 %0, [%1];"
                 : "=r"(v) : "l"(p) : "memory");
    return v;
}
__device__ __forceinline__ float4 ldcg4(const float4* p) {
    float4 u;
    asm volatile("ld.global.cg.v4.f32 {%0,%1,%2,%3}, [%4];"
                 : "=f"(u.x), "=f"(u.y), "=f"(u.z), "=f"(u.w)
                 : "l"(p) : "memory");
    return u;
}

// Barrier wait: double relaxed poll (halved sampling period) + acquire fence.
__device__ __forceinline__ void bar_wait(unsigned target) {
    for (;;) {
        unsigned a = ld_relaxed_gpu(&g_arrive);
        unsigned b = ld_relaxed_gpu(&g_arrive);
        if (a >= target || b >= target) break;
    }
    asm volatile("fence.acq_rel.gpu;" ::: "memory");
}

// ---- k1: U[m][t][j] = x[t,2047,:] @ W_in_m[:,j] + b_m[j]; block 0 also
//      resets the barrier counter and zeroes state (init kernel folded) ----
__global__ __launch_bounds__(256)
void u_kernel(const float* __restrict__ x,
              const float* __restrict__ W_in1, const float* __restrict__ b_in1,
              const float* __restrict__ W_in2, const float* __restrict__ b_in2)
{
    __shared__ float xs[8][256];
    const int b   = blockIdx.x;
    const int tid = threadIdx.x;

    if (b == 0) {
        if (tid == 0) g_arrive = 0u;
        for (int idx = tid; idx < 1024; idx += 256)
            g_z[0][idx] = make_float2(0.0f, 0.0f);
    }

    const int m   = b >> 7;
    const int jt  = (b >> 5) & 3;
    const int t0  = (b & 31) * 8;
    const float* W  = m ? W_in2 : W_in1;
    const float* bi = m ? b_in2 : b_in1;

    for (int i = tid; i < 8 * 256; i += 256) {
        int tr = i >> 8, k = i & 255;
        xs[tr][k] = x[((size_t)(t0 + tr) * 2048 + 2047) * 256 + k];
    }
    __syncthreads();

    const int j = jt * 256 + tid;
    float acc[8];
    const float bj = bi[j];
    #pragma unroll
    for (int r = 0; r < 8; r++) acc[r] = bj;
    #pragma unroll 8
    for (int k = 0; k < 256; k++) {
        float w = W[k * 1024 + j];
        #pragma unroll
        for (int r = 0; r < 8; r++) acc[r] += xs[r][k] * w;
    }
    #pragma unroll
    for (int r = 0; r < 8; r++) g_U[m][t0 + r][j] = acc[r];
}

// ---- k3: out[t][o] = tanh(hist[t] @ W_out[:,o] + b_out[o]) ----
// grid 32, 8 steps per block: W_out streamed 32x total (vs 128x before)
__global__ __launch_bounds__(256)
void out_kernel(const float* __restrict__ W_out,
                const float* __restrict__ b_out,
                float* __restrict__ out)
{
    __shared__ float zs[8][1024];       // 32 KB
    const int t0  = blockIdx.x * 8;
    const int tid = threadIdx.x;
    for (int i = tid; i < 8 * 1024; i += 256)
        zs[i >> 10][i & 1023] = g_hist[t0 + (i >> 10)][i & 1023];
    __syncthreads();

    float acc[8];
    const float bo = b_out[tid];
    #pragma unroll
    for (int r = 0; r < 8; r++) acc[r] = bo;
    #pragma unroll 8
    for (int jj = 0; jj < 1024; jj++) {
        float w = W_out[jj * 256 + tid];
        #pragma unroll
        for (int r = 0; r < 8; r++) acc[r] += zs[r][jj] * w;
    }
    #pragma unroll
    for (int r = 0; r < 8; r++)
        out[(size_t)(t0 + r) * 256 + tid] = tanhf(acc[r]);
}

// ---- k2: persistent recurrence (R7 shape) ----
__global__ __launch_bounds__(BLOCK, 1)
void rnn_main_kernel(const float* __restrict__ W_rec1,
                     const float* __restrict__ W_rec2)
{
    __shared__ float e1[1024];          // z1 + z2
    __shared__ float e2[1024];          // z2
    __shared__ float stage[1024 * 9];   // weight staging (preload only), pad 9

    const int tid  = threadIdx.x;
    const int warp = tid >> 5;
    const int lane = tid & 31;
    const int j0   = blockIdx.x * 8;
    const int role = warp >> 3;         // 0: z1 warps 0-7, 1: z2 warps 8-15
    const int jl   = warp & 7;
    const int j    = j0 + jl;

    // ---- weight preload: wreg[4c+s] = W[(c*128 + lane*4 + s)][j] ----
    float wreg[32];
    for (int round = 0; round < 2; round++) {
        const float* W = round ? W_rec2 : W_rec1;
        for (int idx = tid; idx < 1024 * 8; idx += BLOCK) {
            int k = idx >> 3, c = idx & 7;
            stage[k * 9 + c] = W[k * 1024 + j0 + c];
        }
        __syncthreads();
        if (role == round) {
            #pragma unroll
            for (int c = 0; c < 8; c++) {
                int k0 = c * 128 + lane * 4;
                wreg[4*c+0] = stage[(k0 + 0) * 9 + jl];
                wreg[4*c+1] = stage[(k0 + 1) * 9 + jl];
                wreg[4*c+2] = stage[(k0 + 2) * 9 + jl];
                wreg[4*c+3] = stage[(k0 + 3) * 9 + jl];
            }
        }
        __syncthreads();
    }

    float z2reg = 0.0f;                 // z2 warps, lane-replicated hold value

    for (int i = 0; i < NSTEP; i++) {
        const int par = i & 1;
        const int pw  = par ^ 1;

        // warp-uniform u load (broadcast LDG) — consumed late, mostly hidden
        const float u = g_U[role][i][j];

        // Phase A: reload state once per CTA into SMEM
        {
            float4 q = ldcg4(((const float4*)g_z[par]) + tid);  // {z1a,z2a,z1b,z2b}
            ((float2*)e1)[tid] = make_float2(q.x + q.y, q.z + q.w);
            ((float2*)e2)[tid] = make_float2(q.y, q.w);
        }
        __syncthreads();

        // Phase B: one warp = one full-K dot
        if (role == 0 || (i & 1) == 0) {
            const float4* ev = (const float4*)(role ? e2 : e1);
            float a0 = 0.0f, a1 = 0.0f;
            #pragma unroll
            for (int c = 0; c < 8; c++) {
                float4 q = ev[c * 32 + lane];
                a0 += wreg[4*c+0] * q.x + wreg[4*c+1] * q.y;
                a1 += wreg[4*c+2] * q.z + wreg[4*c+3] * q.w;
            }
            float acc = a0 + a1;
            #pragma unroll
            for (int off = 16; off; off >>= 1)
                acc += __shfl_xor_sync(0xffffffffu, acc, off);
            if (role == 0) {
                if (lane == 0) {
                    float v = tanhf(acc + u);
                    ((float*)&g_z[pw][j])[0] = v;     // z1
                    g_hist[i][j] = v;
                }
            } else {
                z2reg = tanhf(acc + u);               // all lanes (redundant)
                if (lane == 0) ((float*)&g_z[pw][j])[1] = z2reg;
            }
        } else if (lane == 0) {
            ((float*)&g_z[pw][j])[1] = z2reg;         // odd step: z2 holds
        }
        __syncthreads();    // all publishes issued (ordering for tid0's release)

        if (i + 1 < NSTEP) {
            if (tid == 0) {
                arrive_release(&g_arrive);
                bar_wait((unsigned)(i + 1) * GRID);
            }
            __syncthreads();
        }
    }
}

extern "C" void kernel_launch(void* const* d_in, const int* in_sizes, int n_in,
                              void* d_out, int out_size) {
    (void)in_sizes; (void)n_in; (void)out_size;
    const float* x      = (const float*)d_in[0];
    const float* W_in1  = (const float*)d_in[1];
    const float* b_in1  = (const float*)d_in[2];
    const float* W_rec1 = (const float*)d_in[3];
    const float* W_in2  = (const float*)d_in[4];
    const float* b_in2  = (const float*)d_in[5];
    const float* W_rec2 = (const float*)d_in[6];
    const float* W_out  = (const float*)d_in[7];
    const float* b_out  = (const float*)d_in[8];
    float* out = (float*)d_out;

    u_kernel<<<256, 256>>>(x, W_in1, b_in1, W_in2, b_in2);
    rnn_main_kernel<<<GRID, BLOCK>>>(W_rec1, W_rec2);
    out_kernel<<<32, 256>>>(W_out, b_out, out);
}

// round 14
// speedup vs baseline: 1.1057x; 1.1057x over previous
#include <cuda_runtime.h>

// AlarmworkRNN collapsed to a vector RNN (only sequence row 2047 matters).
// Round 14: R13 with the barrier wait reverted to the R7-proven ld.acquire
// poll (R13's fence.acq_rel on the detect path cost ~140us), and u_kernel
// re-blocked to 16 steps/block (2x arithmetic per W load).

#define GRID  128
#define BLOCK 512
#define NSTEP 256

__device__ unsigned g_arrive;
__device__ float2 g_z[2][1024];           // parity-buffered {z1, z2}
__device__ float g_U[2][NSTEP][1024];     // u1/u2 per step (bias folded)
__device__ float g_hist[NSTEP][1024];     // z1 history for out_kernel

__device__ __forceinline__ void arrive_release(unsigned* p) {
    asm volatile("red.release.gpu.global.add.u32 [%0], %1;"
                 :: "l"(p), "r"(1u) : "memory");
}
__device__ __forceinline__ unsigned ld_acquire_gpu(unsigned* p) {
    unsigned v;
    asm volatile("ld.acquire.gpu.global.u32 %0, [%1];"
                 : "=r"(v) : "l"(p) : "memory");
    return v;
}
__device__ __forceinline__ float4 ldcg4(const float4* p) {
    float4 u;
    asm volatile("ld.global.cg.v4.f32 {%0,%1,%2,%3}, [%4];"
                 : "=f"(u.x), "=f"(u.y), "=f"(u.z), "=f"(u.w)
                 : "l"(p) : "memory");
    return u;
}

// ---- k1: U[m][t][j] = x[t,2047,:] @ W_in_m[:,j] + b_m[j] ----
// grid 128: m = b>>6, jt = (b>>4)&3, tt = b&15 (16 steps/block).
// Block 0 also resets barrier counter and zeroes state (init folded).
__global__ __launch_bounds__(256)
void u_kernel(const float* __restrict__ x,
              const float* __restrict__ W_in1, const float* __restrict__ b_in1,
              const float* __restrict__ W_in2, const float* __restrict__ b_in2)
{
    __shared__ float xs[16][256];
    const int b   = blockIdx.x;
    const int tid = threadIdx.x;

    if (b == 0) {
        if (tid == 0) g_arrive = 0u;
        for (int idx = tid; idx < 1024; idx += 256)
            g_z[0][idx] = make_float2(0.0f, 0.0f);
    }

    const int m   = b >> 6;
    const int jt  = (b >> 4) & 3;
    const int t0  = (b & 15) * 16;
    const float* W  = m ? W_in2 : W_in1;
    const float* bi = m ? b_in2 : b_in1;

    for (int i = tid; i < 16 * 256; i += 256) {
        int tr = i >> 8, k = i & 255;
        xs[tr][k] = x[((size_t)(t0 + tr) * 2048 + 2047) * 256 + k];
    }
    __syncthreads();

    const int j = jt * 256 + tid;
    float acc[16];
    const float bj = bi[j];
    #pragma unroll
    for (int r = 0; r < 16; r++) acc[r] = bj;
    #pragma unroll 4
    for (int k = 0; k < 256; k++) {
        float w = W[k * 1024 + j];
        #pragma unroll
        for (int r = 0; r < 16; r++) acc[r] += xs[r][k] * w;
    }
    #pragma unroll
    for (int r = 0; r < 16; r++) g_U[m][t0 + r][j] = acc[r];
}

// ---- k3: out[t][o] = tanh(hist[t] @ W_out[:,o] + b_out[o]) ----
// grid 32, 8 steps per block
__global__ __launch_bounds__(256)
void out_kernel(const float* __restrict__ W_out,
                const float* __restrict__ b_out,
                float* __restrict__ out)
{
    __shared__ float zs[8][1024];       // 32 KB
    const int t0  = blockIdx.x * 8;
    const int tid = threadIdx.x;
    for (int i = tid; i < 8 * 1024; i += 256)
        zs[i >> 10][i & 1023] = g_hist[t0 + (i >> 10)][i & 1023];
    __syncthreads();

    float acc[8];
    const float bo = b_out[tid];
    #pragma unroll
    for (int r = 0; r < 8; r++) acc[r] = bo;
    #pragma unroll 8
    for (int jj = 0; jj < 1024; jj++) {
        float w = W_out[jj * 256 + tid];
        #pragma unroll
        for (int r = 0; r < 8; r++) acc[r] += zs[r][jj] * w;
    }
    #pragma unroll
    for (int r = 0; r < 8; r++)
        out[(size_t)(t0 + r) * 256 + tid] = tanhf(acc[r]);
}

// ---- k2: persistent recurrence (R7 shape, R7 barrier) ----
__global__ __launch_bounds__(BLOCK, 1)
void rnn_main_kernel(const float* __restrict__ W_rec1,
                     const float* __restrict__ W_rec2)
{
    __shared__ float e1[1024];          // z1 + z2
    __shared__ float e2[1024];          // z2
    __shared__ float stage[1024 * 9];   // weight staging (preload only), pad 9

    const int tid  = threadIdx.x;
    const int warp = tid >> 5;
    const int lane = tid & 31;
    const int j0   = blockIdx.x * 8;
    const int role = warp >> 3;         // 0: z1 warps 0-7, 1: z2 warps 8-15
    const int jl   = warp & 7;
    const int j    = j0 + jl;

    // ---- weight preload: wreg[4c+s] = W[(c*128 + lane*4 + s)][j] ----
    float wreg[32];
    for (int round = 0; round < 2; round++) {
        const float* W = round ? W_rec2 : W_rec1;
        for (int idx = tid; idx < 1024 * 8; idx += BLOCK) {
            int k = idx >> 3, c = idx & 7;
            stage[k * 9 + c] = W[k * 1024 + j0 + c];
        }
        __syncthreads();
        if (role == round) {
            #pragma unroll
            for (int c = 0; c < 8; c++) {
                int k0 = c * 128 + lane * 4;
                wreg[4*c+0] = stage[(k0 + 0) * 9 + jl];
                wreg[4*c+1] = stage[(k0 + 1) * 9 + jl];
                wreg[4*c+2] = stage[(k0 + 2) * 9 + jl];
                wreg[4*c+3] = stage[(k0 + 3) * 9 + jl];
            }
        }
        __syncthreads();
    }

    float z2reg = 0.0f;                 // z2 warps, lane-replicated hold value

    for (int i = 0; i < NSTEP; i++) {
        const int par = i & 1;
        const int pw  = par ^ 1;

        // warp-uniform u load (broadcast LDG) — consumed late, mostly hidden
        const float u = g_U[role][i][j];

        // Phase A: reload state once per CTA into SMEM
        {
            float4 q = ldcg4(((const float4*)g_z[par]) + tid);  // {z1a,z2a,z1b,z2b}
            ((float2*)e1)[tid] = make_float2(q.x + q.y, q.z + q.w);
            ((float2*)e2)[tid] = make_float2(q.y, q.w);
        }
        __syncthreads();

        // Phase B: one warp = one full-K dot
        if (role == 0 || (i & 1) == 0) {
            const float4* ev = (const float4*)(role ? e2 : e1);
            float a0 = 0.0f, a1 = 0.0f;
            #pragma unroll
            for (int c = 0; c < 8; c++) {
                float4 q = ev[c * 32 + lane];
                a0 += wreg[4*c+0] * q.x + wreg[4*c+1] * q.y;
                a1 += wreg[4*c+2] * q.z + wreg[4*c+3] * q.w;
            }
            float acc = a0 + a1;
            #pragma unroll
            for (int off = 16; off; off >>= 1)
                acc += __shfl_xor_sync(0xffffffffu, acc, off);
            if (role == 0) {
                if (lane == 0) {
                    float v = tanhf(acc + u);
                    ((float*)&g_z[pw][j])[0] = v;     // z1
                    g_hist[i][j] = v;
                }
            } else {
                z2reg = tanhf(acc + u);               // all lanes (redundant)
                if (lane == 0) ((float*)&g_z[pw][j])[1] = z2reg;
            }
        } else if (lane == 0) {
            ((float*)&g_z[pw][j])[1] = z2reg;         // odd step: z2 holds
        }
        __syncthreads();    // all publishes issued (ordering for tid0's release)

        if (i + 1 < NSTEP) {
            if (tid == 0) {
                arrive_release(&g_arrive);
                const unsigned target = (unsigned)(i + 1) * GRID;
                while (ld_acquire_gpu(&g_arrive) < target) { }
            }
            __syncthreads();
        }
    }
}

extern "C" void kernel_launch(void* const* d_in, const int* in_sizes, int n_in,
                              void* d_out, int out_size) {
    (void)in_sizes; (void)n_in; (void)out_size;
    const float* x      = (const float*)d_in[0];
    const float* W_in1  = (const float*)d_in[1];
    const float* b_in1  = (const float*)d_in[2];
    const float* W_rec1 = (const float*)d_in[3];
    const float* W_in2  = (const float*)d_in[4];
    const float* b_in2  = (const float*)d_in[5];
    const float* W_rec2 = (const float*)d_in[6];
    const float* W_out  = (const float*)d_in[7];
    const float* b_out  = (const float*)d_in[8];
    float* out = (float*)d_out;

    u_kernel<<<128, 256>>>(x, W_in1, b_in1, W_in2, b_in2);
    rnn_main_kernel<<<GRID, BLOCK>>>(W_rec1, W_rec2);
    out_kernel<<<32, 256>>>(W_out, b_out, out);
}

// round 15
// speedup vs baseline: 1.1081x; 1.0021x over previous
#include <cuda_runtime.h>

// AlarmworkRNN collapsed to a vector RNN (only sequence row 2047 matters).
// Round 15: best-of-each-round assembly.
//   u_kernel: grid 256 (R7-proven 44.5us; grid-128 variant was 73.5us),
//             init folded into block 0.
//   main:     R7 shape (proven-fastest ~444us) + dedicated barrier warp 16.
//   out:      grid 32, 8 steps/block (R13 shape).

#define GRID  128
#define BLOCK 544          // 16 compute warps + 1 barrier warp
#define NSTEP 256

__device__ unsigned g_arrive;
__device__ float2 g_z[2][1024];           // parity-buffered {z1, z2}
__device__ float g_U[2][NSTEP][1024];     // u1/u2 per step (bias folded)
__device__ float g_hist[NSTEP][1024];     // z1 history for out_kernel

__device__ __forceinline__ void arrive_release(unsigned* p) {
    asm volatile("red.release.gpu.global.add.u32 [%0], %1;"
                 :: "l"(p), "r"(1u) : "memory");
}
__device__ __forceinline__ unsigned ld_acquire_gpu(unsigned* p) {
    unsigned v;
    asm volatile("ld.acquire.gpu.global.u32 %0, [%1];"
                 : "=r"(v) : "l"(p) : "memory");
    return v;
}
__device__ __forceinline__ float4 ldcg4(const float4* p) {
    float4 u;
    asm volatile("ld.global.cg.v4.f32 {%0,%1,%2,%3}, [%4];"
                 : "=f"(u.x), "=f"(u.y), "=f"(u.z), "=f"(u.w)
                 : "l"(p) : "memory");
    return u;
}

// ---- k1: U[m][t][j] = x[t,2047,:] @ W_in_m[:,j] + b_m[j] ----
// grid 256 (8 steps/block — proven fastest); block 0 folds init.
__global__ __launch_bounds__(256)
void u_kernel(const float* __restrict__ x,
              const float* __restrict__ W_in1, const float* __restrict__ b_in1,
              const float* __restrict__ W_in2, const float* __restrict__ b_in2)
{
    __shared__ float xs[8][256];
    const int b   = blockIdx.x;
    const int tid = threadIdx.x;

    if (b == 0) {
        if (tid == 0) g_arrive = 0u;
        for (int idx = tid; idx < 1024; idx += 256)
            g_z[0][idx] = make_float2(0.0f, 0.0f);
    }

    const int m   = b >> 7;
    const int jt  = (b >> 5) & 3;
    const int t0  = (b & 31) * 8;
    const float* W  = m ? W_in2 : W_in1;
    const float* bi = m ? b_in2 : b_in1;

    for (int i = tid; i < 8 * 256; i += 256) {
        int tr = i >> 8, k = i & 255;
        xs[tr][k] = x[((size_t)(t0 + tr) * 2048 + 2047) * 256 + k];
    }
    __syncthreads();

    const int j = jt * 256 + tid;
    float acc[8];
    const float bj = bi[j];
    #pragma unroll
    for (int r = 0; r < 8; r++) acc[r] = bj;
    #pragma unroll 8
    for (int k = 0; k < 256; k++) {
        float w = W[k * 1024 + j];
        #pragma unroll
        for (int r = 0; r < 8; r++) acc[r] += xs[r][k] * w;
    }
    #pragma unroll
    for (int r = 0; r < 8; r++) g_U[m][t0 + r][j] = acc[r];
}

// ---- k3: out[t][o] = tanh(hist[t] @ W_out[:,o] + b_out[o]) ----
// grid 32, 8 steps per block
__global__ __launch_bounds__(256)
void out_kernel(const float* __restrict__ W_out,
                const float* __restrict__ b_out,
                float* __restrict__ out)
{
    __shared__ float zs[8][1024];       // 32 KB
    const int t0  = blockIdx.x * 8;
    const int tid = threadIdx.x;
    for (int i = tid; i < 8 * 1024; i += 256)
        zs[i >> 10][i & 1023] = g_hist[t0 + (i >> 10)][i & 1023];
    __syncthreads();

    float acc[8];
    const float bo = b_out[tid];
    #pragma unroll
    for (int r = 0; r < 8; r++) acc[r] = bo;
    #pragma unroll 8
    for (int jj = 0; jj < 1024; jj++) {
        float w = W_out[jj * 256 + tid];
        #pragma unroll
        for (int r = 0; r < 8; r++) acc[r] += zs[r][jj] * w;
    }
    #pragma unroll
    for (int r = 0; r < 8; r++)
        out[(size_t)(t0 + r) * 256 + tid] = tanhf(acc[r]);
}

// ---- k2: persistent recurrence (R7 shape + dedicated barrier warp) ----
__global__ __launch_bounds__(BLOCK, 1)
void rnn_main_kernel(const float* __restrict__ W_rec1,
                     const float* __restrict__ W_rec2)
{
    __shared__ float e1[1024];          // z1 + z2
    __shared__ float e2[1024];          // z2
    __shared__ float stage[1024 * 9];   // weight staging (preload only), pad 9

    const int tid  = threadIdx.x;
    const int warp = tid >> 5;
    const int lane = tid & 31;
    const int j0   = blockIdx.x * 8;
    const int role = warp >> 3;         // 0: z1 warps 0-7, 1: z2 warps 8-15, 2: barrier
    const int jl   = warp & 7;
    const int j    = j0 + jl;

    // ---- weight preload: wreg[4c+s] = W[(c*128 + lane*4 + s)][j] ----
    float wreg[32];
    for (int round = 0; round < 2; round++) {
        const float* W = round ? W_rec2 : W_rec1;
        for (int idx = tid; idx < 1024 * 8; idx += BLOCK) {
            int k = idx >> 3, c = idx & 7;
            stage[k * 9 + c] = W[k * 1024 + j0 + c];
        }
        __syncthreads();
        if (role == round) {
            #pragma unroll
            for (int c = 0; c < 8; c++) {
                int k0 = c * 128 + lane * 4;
                wreg[4*c+0] = stage[(k0 + 0) * 9 + jl];
                wreg[4*c+1] = stage[(k0 + 1) * 9 + jl];
                wreg[4*c+2] = stage[(k0 + 2) * 9 + jl];
                wreg[4*c+3] = stage[(k0 + 3) * 9 + jl];
            }
        }
        __syncthreads();
    }

    float z2reg = 0.0f;                 // z2 warps, lane-replicated hold value

    for (int i = 0; i < NSTEP; i++) {
        const int par = i & 1;
        const int pw  = par ^ 1;

        // warp-uniform u load (broadcast LDG) — consumed late, mostly hidden
        const float u = (role < 2) ? g_U[role][i][j] : 0.0f;

        // Phase A: reload state once per CTA into SMEM (512 loader threads)
        if (tid < 512) {
            float4 q = ldcg4(((const float4*)g_z[par]) + tid);  // {z1a,z2a,z1b,z2b}
            ((float2*)e1)[tid] = make_float2(q.x + q.y, q.z + q.w);
            ((float2*)e2)[tid] = make_float2(q.y, q.w);
        }
        __syncthreads();

        // Phase B: one warp = one full-K dot
        if (role == 0 || (role == 1 && (i & 1) == 0)) {
            const float4* ev = (const float4*)(role ? e2 : e1);
            float a0 = 0.0f, a1 = 0.0f;
            #pragma unroll
            for (int c = 0; c < 8; c++) {
                float4 q = ev[c * 32 + lane];
                a0 += wreg[4*c+0] * q.x + wreg[4*c+1] * q.y;
                a1 += wreg[4*c+2] * q.z + wreg[4*c+3] * q.w;
            }
            float acc = a0 + a1;
            #pragma unroll
            for (int off = 16; off; off >>= 1)
                acc += __shfl_xor_sync(0xffffffffu, acc, off);
            if (role == 0) {
                if (lane == 0) {
                    float v = tanhf(acc + u);
                    ((float*)&g_z[pw][j])[0] = v;     // z1
                    g_hist[i][j] = v;
                }
            } else {
                z2reg = tanhf(acc + u);               // all lanes (redundant)
                if (lane == 0) ((float*)&g_z[pw][j])[1] = z2reg;
            }
        } else if (role == 1 && lane == 0) {
            ((float*)&g_z[pw][j])[1] = z2reg;         // odd step: z2 holds
        }
        __syncthreads();    // all publishes issued (ordering for poll warp's release)

        if (i + 1 < NSTEP) {
            if (warp == 16 && lane == 0) {            // dedicated barrier warp
                arrive_release(&g_arrive);
                const unsigned target = (unsigned)(i + 1) * GRID;
                while (ld_acquire_gpu(&g_arrive) < target) { }
            }
            __syncthreads();
        }
    }
}

extern "C" void kernel_launch(void* const* d_in, const int* in_sizes, int n_in,
                              void* d_out, int out_size) {
    (void)in_sizes; (void)n_in; (void)out_size;
    const float* x      = (const float*)d_in[0];
    const float* W_in1  = (const float*)d_in[1];
    const float* b_in1  = (const float*)d_in[2];
    const float* W_rec1 = (const float*)d_in[3];
    const float* W_in2  = (const float*)d_in[4];
    const float* b_in2  = (const float*)d_in[5];
    const float* W_rec2 = (const float*)d_in[6];
    const float* W_out  = (const float*)d_in[7];
    const float* b_out  = (const float*)d_in[8];
    float* out = (float*)d_out;

    u_kernel<<<256, 256>>>(x, W_in1, b_in1, W_in2, b_in2);
    rnn_main_kernel<<<GRID, BLOCK>>>(W_rec1, W_rec2);
    out_kernel<<<32, 256>>>(W_out, b_out, out);
}

// round 16
// speedup vs baseline: 1.2197x; 1.1008x over previous
#include <cuda_runtime.h>

// AlarmworkRNN collapsed to a vector RNN (only sequence row 2047 matters).
// Round 16: R12 (best measured, 536.6us) with u_kernel re-parameterized to
// grid 512 x 4 steps/block (u is parallelism-bound: 128->73us, 256->45us).
// Main kernel byte-identical to R12: out-GEMV folded into odd steps' idle
// z2-warps, odd-step split barrier, R7 counter barrier, init folded into u.

#define GRID  128
#define BLOCK 512
#define NSTEP 256

__device__ unsigned g_arrive;
__device__ float2 g_z[2][1024];           // parity-buffered {z1, z2}
__device__ float g_U[2][NSTEP][1024];     // u1/u2 per step (bias folded)

__device__ __forceinline__ void arrive_release(unsigned* p) {
    asm volatile("red.release.gpu.global.add.u32 [%0], %1;"
                 :: "l"(p), "r"(1u) : "memory");
}
__device__ __forceinline__ unsigned ld_acquire_gpu(unsigned* p) {
    unsigned v;
    asm volatile("ld.acquire.gpu.global.u32 %0, [%1];"
                 : "=r"(v) : "l"(p) : "memory");
    return v;
}
__device__ __forceinline__ float4 ldcg4(const float4* p) {
    float4 u;
    asm volatile("ld.global.cg.v4.f32 {%0,%1,%2,%3}, [%4];"
                 : "=f"(u.x), "=f"(u.y), "=f"(u.z), "=f"(u.w)
                 : "l"(p) : "memory");
    return u;
}
#define BAR_SYNC(id, n)   asm volatile("bar.sync %0, %1;"   :: "r"(id), "r"(n) : "memory")
#define BAR_ARRIVE(id, n) asm volatile("bar.arrive %0, %1;" :: "r"(id), "r"(n) : "memory")

// ---- k1: U[m][t][j] = x[t,2047,:] @ W_in_m[:,j] + b_m[j] ----
// grid 512: m = b>>8, jt = (b>>6)&3, t0 = (b&63)*4 (4 steps/block).
// Block 0 also resets barrier counter and zeroes state (init folded).
__global__ __launch_bounds__(256)
void u_kernel(const float* __restrict__ x,
              const float* __restrict__ W_in1, const float* __restrict__ b_in1,
              const float* __restrict__ W_in2, const float* __restrict__ b_in2)
{
    __shared__ float xs[4][256];
    const int b   = blockIdx.x;
    const int tid = threadIdx.x;

    if (b == 0) {
        if (tid == 0) g_arrive = 0u;
        for (int idx = tid; idx < 1024; idx += 256)
            g_z[0][idx] = make_float2(0.0f, 0.0f);
    }

    const int m   = b >> 8;
    const int jt  = (b >> 6) & 3;
    const int t0  = (b & 63) * 4;
    const float* W  = m ? W_in2 : W_in1;
    const float* bi = m ? b_in2 : b_in1;

    for (int i = tid; i < 4 * 256; i += 256) {
        int tr = i >> 8, k = i & 255;
        xs[tr][k] = x[((size_t)(t0 + tr) * 2048 + 2047) * 256 + k];
    }
    __syncthreads();

    const int j = jt * 256 + tid;
    float acc[4];
    const float bj = bi[j];
    #pragma unroll
    for (int r = 0; r < 4; r++) acc[r] = bj;
    #pragma unroll 8
    for (int k = 0; k < 256; k++) {
        float w = W[k * 1024 + j];
        #pragma unroll
        for (int r = 0; r < 4; r++) acc[r] += xs[r][k] * w;
    }
    #pragma unroll
    for (int r = 0; r < 4; r++) g_U[m][t0 + r][j] = acc[r];
}

// ---- k2: persistent recurrence + in-loop out (R12, unchanged) ----
__global__ __launch_bounds__(BLOCK, 1)
void rnn_main_kernel(const float* __restrict__ W_rec1,
                     const float* __restrict__ W_rec2,
                     const float* __restrict__ W_out,
                     const float* __restrict__ b_out,
                     float* __restrict__ out)
{
    extern __shared__ float sm[];
    float* e1     = sm;                 // [1024]  z1 + z2
    float* e2     = e1 + 1024;          // [1024]  z2
    float* z1s    = e2 + 1024;          // [2][1024] z1 snapshots by parity
    float* wout_s = z1s + 2048;         // [2][1024] this CTA's W_out columns
    float* stage  = wout_s + 2048;      // [1024*9] weight staging (preload only)

    const int tid  = threadIdx.x;
    const int warp = tid >> 5;
    const int lane = tid & 31;
    const int j0   = blockIdx.x * 8;
    const int o0   = blockIdx.x * 2;
    const int role = warp >> 3;         // 0: z1 warps 0-7, 1: z2 warps 8-15
    const int jl   = warp & 7;
    const int j    = j0 + jl;

    // ---- preload recurrent weights into registers ----
    float wreg[32];
    for (int round = 0; round < 2; round++) {
        const float* W = round ? W_rec2 : W_rec1;
        for (int idx = tid; idx < 1024 * 8; idx += BLOCK) {
            int k = idx >> 3, c = idx & 7;
            stage[k * 9 + c] = W[k * 1024 + j0 + c];
        }
        __syncthreads();
        if (role == round) {
            #pragma unroll
            for (int c = 0; c < 8; c++) {
                int k0 = c * 128 + lane * 4;
                wreg[4*c+0] = stage[(k0 + 0) * 9 + jl];
                wreg[4*c+1] = stage[(k0 + 1) * 9 + jl];
                wreg[4*c+2] = stage[(k0 + 2) * 9 + jl];
                wreg[4*c+3] = stage[(k0 + 3) * 9 + jl];
            }
        }
        __syncthreads();
    }

    // preload this CTA's two W_out columns + biases into SMEM
    for (int idx = tid; idx < 2048; idx += BLOCK) {
        int jj = idx >> 1, c = idx & 1;
        wout_s[c * 1024 + jj] = W_out[jj * 256 + o0 + c];
    }
    const int   ow   = warp - 8;                 // out-warp id 0..3 (warps 8-11)
    const float obia = (ow >= 0 && ow < 4) ? b_out[o0 + (ow & 1)] : 0.0f;
    __syncthreads();

    float z2reg = 0.0f;

    for (int i = 0; i < NSTEP; i++) {
        const int par = i & 1;
        const int pw  = par ^ 1;

        const float u = g_U[role][i][j];   // warp-uniform broadcast

        // Phase A: stage state into SMEM (+ z1 snapshot for out-GEMV)
        {
            float4 q = ldcg4(((const float4*)g_z[par]) + tid); // {z1a,z2a,z1b,z2b}
            ((float2*)e1)[tid]  = make_float2(q.x + q.y, q.z + q.w);
            ((float2*)e2)[tid]  = make_float2(q.y, q.w);
            ((float2*)(z1s + par * 1024))[tid] = make_float2(q.x, q.z);
        }
        __syncthreads();

        if ((i & 1) == 0) {
            // ---- EVEN step: both recurrent dots, standard barrier ----
            const float4* ev = (const float4*)(role ? e2 : e1);
            float a0 = 0.0f, a1 = 0.0f;
            #pragma unroll
            for (int c = 0; c < 8; c++) {
                float4 q = ev[c * 32 + lane];
                a0 += wreg[4*c+0] * q.x + wreg[4*c+1] * q.y;
                a1 += wreg[4*c+2] * q.z + wreg[4*c+3] * q.w;
            }
            float acc = a0 + a1;
            #pragma unroll
            for (int off = 16; off; off >>= 1)
                acc += __shfl_xor_sync(0xffffffffu, acc, off);
            if (role == 0) {
                if (lane == 0) ((float*)&g_z[pw][j])[0] = tanhf(acc + u);
            } else {
                z2reg = tanhf(acc + u);
                if (lane == 0) ((float*)&g_z[pw][j])[1] = z2reg;
            }
            __syncthreads();   // all publishes issued before arrive
            if (i + 1 < NSTEP) {
                if (tid == 0) {
                    arrive_release(&g_arrive);
                    const unsigned target = (unsigned)(i + 1) * GRID;
                    while (ld_acquire_gpu(&g_arrive) < target) { }
                }
            }
            __syncthreads();
        } else {
            // ---- ODD step: z2 holds; split barrier; out-GEMV in wait window ----
            if (warp < 8) {
                // z1 GEMV + publish, then gate the arrive
                const float4* ev = (const float4*)e1;
                float a0 = 0.0f, a1 = 0.0f;
                #pragma unroll
                for (int c = 0; c < 8; c++) {
                    float4 q = ev[c * 32 + lane];
                    a0 += wreg[4*c+0] * q.x + wreg[4*c+1] * q.y;
                    a1 += wreg[4*c+2] * q.z + wreg[4*c+3] * q.w;
                }
                float acc = a0 + a1;
                #pragma unroll
                for (int off = 16; off; off >>= 1)
                    acc += __shfl_xor_sync(0xffffffffu, acc, off);
                if (lane == 0) ((float*)&g_z[pw][j])[0] = tanhf(acc + u);
                BAR_SYNC(1, BLOCK);
                if (i + 1 < NSTEP && tid == 0) {
                    arrive_release(&g_arrive);
                    const unsigned target = (unsigned)(i + 1) * GRID;
                    while (ld_acquire_gpu(&g_arrive) < target) { }
                }
            } else {
                // z2 hold publish (register, instant), arrive without blocking,
                // then out-GEMV concurrent with the global barrier
                if (lane == 0) ((float*)&g_z[pw][j])[1] = z2reg;
                BAR_ARRIVE(1, BLOCK);
                if (ow < 4) {
                    const int t_sel = ow >> 1;       // 0: out[i-2], 1: out[i-1]
                    const int o_sel = ow & 1;
                    if (!(t_sel == 0 && i == 1)) {
                        const float4* wv = (const float4*)(wout_s + o_sel * 1024);
                        const float4* zv = (const float4*)(z1s + t_sel * 1024);
                        float a0 = 0.0f, a1 = 0.0f;
                        #pragma unroll
                        for (int c = 0; c < 8; c++) {
                            float4 wq = wv[c * 32 + lane];
                            float4 zq = zv[c * 32 + lane];
                            a0 += wq.x * zq.x + wq.y * zq.y;
                            a1 += wq.z * zq.z + wq.w * zq.w;
                        }
                        float acc = a0 + a1;
                        #pragma unroll
                        for (int off = 16; off; off >>= 1)
                            acc += __shfl_xor_sync(0xffffffffu, acc, off);
                        if (lane == 0)
                            out[(size_t)(i - 2 + t_sel) * 256 + o0 + o_sel] =
                                tanhf(acc + obia);
                    }
                }
            }
            __syncthreads();   // everyone meets before next Phase A
        }
    }

    // Tail: final barrier round, then out[255] from z1(256)
    if (tid == 0) {
        arrive_release(&g_arrive);
        const unsigned target = (unsigned)NSTEP * GRID;
        while (ld_acquire_gpu(&g_arrive) < target) { }
    }
    __syncthreads();
    {
        float4 q = ldcg4(((const float4*)g_z[0]) + tid);   // z(256) lives in g_z[0]
        ((float2*)z1s)[tid] = make_float2(q.x, q.z);
        __syncthreads();
        if (ow == 0 || ow == 1) {          // warps 8, 9
            const float4* wv = (const float4*)(wout_s + ow * 1024);
            const float4* zv = (const float4*)z1s;
            float a0 = 0.0f, a1 = 0.0f;
            #pragma unroll
            for (int c = 0; c < 8; c++) {
                float4 wq = wv[c * 32 + lane];
                float4 zq = zv[c * 32 + lane];
                a0 += wq.x * zq.x + wq.y * zq.y;
                a1 += wq.z * zq.z + wq.w * zq.w;
            }
            float acc = a0 + a1;
            #pragma unroll
            for (int off = 16; off; off >>= 1)
                acc += __shfl_xor_sync(0xffffffffu, acc, off);
            if (lane == 0)
                out[(size_t)255 * 256 + o0 + ow] = tanhf(acc + b_out[o0 + ow]);
        }
    }
}

extern "C" void kernel_launch(void* const* d_in, const int* in_sizes, int n_in,
                              void* d_out, int out_size) {
    (void)in_sizes; (void)n_in; (void)out_size;
    const float* x      = (const float*)d_in[0];
    const float* W_in1  = (const float*)d_in[1];
    const float* b_in1  = (const float*)d_in[2];
    const float* W_rec1 = (const float*)d_in[3];
    const float* W_in2  = (const float*)d_in[4];
    const float* b_in2  = (const float*)d_in[5];
    const float* W_rec2 = (const float*)d_in[6];
    const float* W_out  = (const float*)d_in[7];
    const float* b_out  = (const float*)d_in[8];
    float* out = (float*)d_out;

    const size_t smem_bytes =
        (size_t)(1024 + 1024 + 2048 + 2048 + 1024 * 9) * sizeof(float); // 61.4 KB
    cudaFuncSetAttribute(rnn_main_kernel,
                         cudaFuncAttributeMaxDynamicSharedMemorySize,
                         (int)smem_bytes);

    u_kernel<<<512, 256>>>(x, W_in1, b_in1, W_in2, b_in2);
    rnn_main_kernel<<<GRID, BLOCK, smem_bytes>>>(W_rec1, W_rec2, W_out, b_out, out);
}